// round 15
// baseline (speedup 1.0000x reference)
#include <cuda_runtime.h>

#define VOC   96
#define BS    16
#define NQ    200
#define NPTS  25
#define NGT   32
#define LSEQ  25
#define NCOLS (BS*NGT)      /* 512 */
#define CDIM  256
#define QT    4

typedef unsigned long long u64;
#define ABSM 0x7FFFFFFF7FFFFFFFULL

// ---------------- scratch (static device globals; no allocation) ------------
__device__ float  g_soft[VOC*VOC];
__device__ float4 g_tgtT4[13*NCOLS];   // transposed+padded NEGATED tgt pts
__device__ float  g_T[BS*NGT*VOC];     // normalized T rows
__device__ float  g_stt[NCOLS];
__device__ int    g_len[NCOLS];
__device__ int    g_p1;                // stage-1 counter (target 128)
__device__ int    g_pb[BS];            // per-batch T counters (target 2 each)

// ---------------- helpers ----------------------------------------------------
__device__ __forceinline__ u64 pack2(float lo, float hi) {
    u64 r; asm("mov.b64 %0, {%1, %2};" : "=l"(r) : "f"(lo), "f"(hi)); return r;
}
__device__ __forceinline__ u64 add2(u64 a, u64 b) {
    u64 r; asm("add.rn.f32x2 %0, %1, %2;" : "=l"(r) : "l"(a), "l"(b)); return r;
}
__device__ __forceinline__ void unpack2(float& lo, float& hi, u64 a) {
    asm("mov.b64 {%0, %1}, %2;" : "=f"(lo), "=f"(hi) : "l"(a));
}
__device__ __forceinline__ int ld_cg(const int* p) {
    int v; asm volatile("ld.global.cg.s32 %0, [%1];" : "=r"(v) : "l"(p)); return v;
}

// ---------------- kernel 0: reset flags (graph replays persist globals) -----
__global__ void k_init() {
    int t = threadIdx.x;
    if (t == 0) g_p1 = 0;
    if (t < BS) g_pb[t] = 0;
}

// ---------------- kernel 1: everything ---------------------------------------
__global__ void __launch_bounds__(512, 4) k_all(
    const float* __restrict__ txt,      // pred_text_logits [16,200,25,97]
    const float* __restrict__ logits,   // pred_logits      [16,200,25]
    const float* __restrict__ predpts,  // pred_ctrl_points [16,200,50]
    const float* __restrict__ tgtpts,   // tgt_ctrl_points  [512,50]
    const int*   __restrict__ texts,    // tgt_texts        [512,25]
    const float* __restrict__ centroids,// [96,256]
    float* __restrict__ out)            // [16,200,512]
{
    __shared__ float  Pw[16][100];
    __shared__ float  logPs[QT][VOC];
    __shared__ float2 pp2[2*52];
    __shared__ float  Ts[NGT*97];
    __shared__ int    stext[16*LSEQ];
    __shared__ float  stt[NGT];
    __shared__ int    sl[NGT];
    __shared__ float  cls[QT];
    __shared__ float  kls[QT*NGT];
    __shared__ float  fc[QT*NPTS];
    __shared__ float  ci[CDIM];
    __shared__ float  srow[VOC], nrow[VOC], stage[VOC];
    __shared__ float  bc1;

    int b   = blockIdx.y;
    int qb  = blockIdx.x;
    int lid = b*50 + qb;            // linear bid, 0..799
    int q0  = qb*QT;
    int t   = threadIdx.x, w = t >> 5, lane = t & 31;
    bool isTprod = (lid >= 128 && lid < 160);

    // ============ producer stage 1 (lids 0..127): soft rows + transpose =====
    if (lid < 128) {
        if (t < 4*52) {
            int gg = t / 52, d = t - gg*52;
            int grp = lid*4 + gg;
            float v = (d < 50) ? -tgtpts[grp*50 + d] : 0.0f;   // NEGATED
            ((float*)g_tgtT4)[(size_t)((d >> 2)*NCOLS + grp)*4 + (d & 3)] = v;
        }
        if (lid < 96) {
            int i = lid;            // soft_all row i
            if (t < CDIM) ci[t] = centroids[i*CDIM + t];
            __syncthreads();
            float dot[6], nrm[6];
            #pragma unroll
            for (int jj = 0; jj < 6; jj++) { dot[jj] = 0.f; nrm[jj] = 0.f; }
            #pragma unroll
            for (int u = 0; u < 8; u++) {
                float a = ci[lane + u*32];
                #pragma unroll
                for (int jj = 0; jj < 6; jj++) {
                    float bv = centroids[(w + 16*jj)*CDIM + lane + u*32];
                    dot[jj] = fmaf(a,  bv, dot[jj]);
                    nrm[jj] = fmaf(bv, bv, nrm[jj]);
                }
            }
            #pragma unroll
            for (int o = 16; o; o >>= 1) {
                #pragma unroll
                for (int jj = 0; jj < 6; jj++) {
                    dot[jj] += __shfl_xor_sync(0xffffffffu, dot[jj], o);
                    nrm[jj] += __shfl_xor_sync(0xffffffffu, nrm[jj], o);
                }
            }
            if (lane == 0) {
                #pragma unroll
                for (int jj = 0; jj < 6; jj++) {
                    srow[w + 16*jj] = dot[jj];
                    nrow[w + 16*jj] = nrm[jj];
                }
            }
            __syncthreads();
            float e = 0.f;
            if (t < VOC) {
                float sv = srow[t] * rsqrtf(nrow[t] * nrow[i]); // cos in [-1,1]
                e = __expf(sv);                                 // no max needed
                stage[t] = e;
            }
            __syncthreads();
            if (w == 0) {
                float s = stage[lane] + stage[lane+32] + stage[lane+64];
                #pragma unroll
                for (int o = 16; o; o >>= 1) s += __shfl_xor_sync(0xffffffffu, s, o);
                if (lane == 0) bc1 = s;
            }
            __syncthreads();
            if (t < VOC)
                g_soft[i*VOC + t] = (t == i ? 0.85f : 0.0f) + 0.15f * (e / bc1);
        }
        __threadfence();
        __syncthreads();
        if (t == 0) atomicAdd(&g_p1, 1);
    }

    // ============ phase 0: side-data preload =================================
    if (t < 2*52) {
        int pair = t / 52, d = t - pair*52;
        float v0 = 0.f, v1 = 0.f;
        if (d < 50) {
            v0 = predpts[(size_t)(b*NQ + q0 + 2*pair)*50 + d];
            v1 = predpts[(size_t)(b*NQ + q0 + 2*pair + 1)*50 + d];
        }
        pp2[t] = make_float2(v0, v1);
    }
    if (t < QT*NPTS) {
        float x  = logits[(size_t)(b*NQ + q0)*NPTS + t];
        float pr = __fdividef(1.0f, 1.0f + __expf(-x));
        float pos = 0.25f * (1.f - pr) * (1.f - pr) * (-__logf(pr + 1e-8f));
        float neg = 0.75f * pr * pr * (-__logf(1.f - pr + 1e-8f));
        fc[t] = pos - neg;
    }
    if (isTprod) {
        int bb = (lid - 128) >> 1, half = (lid - 128) & 1;
        for (int k = t; k < 16*LSEQ; k += 512)
            stext[k] = texts[((size_t)bb*NGT + half*16)*LSEQ + k];
    }

    // ============ phase 1: register softmax, 4 warps/query, 2 rows in flight =
    {
        int q = w >> 2;
        const float* base = txt + (size_t)(b*NQ + q0 + q) * NPTS * (VOC + 1);
        float pv0 = 0.f, pv1 = 0.f, pv2 = 0.f;
        int p = (w & 3);
        for (; p + 4 < NPTS; p += 8) {
            const float* rA = base + p*(VOC + 1);
            const float* rB = base + (p + 4)*(VOC + 1);
            float a0 = __expf(rA[lane]);
            float a1 = __expf(rA[lane + 32]);
            float a2 = __expf(rA[lane + 64]);
            float a3 = (lane == 0) ? __expf(rA[96]) : 0.f;
            float b0 = __expf(rB[lane]);
            float b1 = __expf(rB[lane + 32]);
            float b2 = __expf(rB[lane + 64]);
            float b3 = (lane == 0) ? __expf(rB[96]) : 0.f;
            float sa = a0 + a1 + a2 + a3;
            float sb = b0 + b1 + b2 + b3;
            #pragma unroll
            for (int o = 16; o; o >>= 1) {
                sa += __shfl_xor_sync(0xffffffffu, sa, o);
                sb += __shfl_xor_sync(0xffffffffu, sb, o);
            }
            float ia = __fdividef(1.0f, sa);
            float ib = __fdividef(1.0f, sb);
            pv0 = fmaf(a0, ia, pv0); pv0 = fmaf(b0, ib, pv0);
            pv1 = fmaf(a1, ia, pv1); pv1 = fmaf(b1, ib, pv1);
            pv2 = fmaf(a2, ia, pv2); pv2 = fmaf(b2, ib, pv2);
        }
        if (p < NPTS) {
            const float* rA = base + p*(VOC + 1);
            float a0 = __expf(rA[lane]);
            float a1 = __expf(rA[lane + 32]);
            float a2 = __expf(rA[lane + 64]);
            float a3 = (lane == 0) ? __expf(rA[96]) : 0.f;
            float sa = a0 + a1 + a2 + a3;
            #pragma unroll
            for (int o = 16; o; o >>= 1) sa += __shfl_xor_sync(0xffffffffu, sa, o);
            float ia = __fdividef(1.0f, sa);
            pv0 = fmaf(a0, ia, pv0);
            pv1 = fmaf(a1, ia, pv1);
            pv2 = fmaf(a2, ia, pv2);
        }
        Pw[w][lane]      = pv0;
        Pw[w][lane + 32] = pv1;
        Pw[w][lane + 64] = pv2;
    }
    __syncthreads();

    // ============ phase 2: logP (warps 0-3), cls (warps 4-7) =================
    if (w < QT) {
        float a0 = (Pw[4*w][lane]      + Pw[4*w+1][lane]      + Pw[4*w+2][lane]      + Pw[4*w+3][lane])      * (1.0f/25.0f) + 1e-6f;
        float a1 = (Pw[4*w][lane + 32] + Pw[4*w+1][lane + 32] + Pw[4*w+2][lane + 32] + Pw[4*w+3][lane + 32]) * (1.0f/25.0f) + 1e-6f;
        float a2 = (Pw[4*w][lane + 64] + Pw[4*w+1][lane + 64] + Pw[4*w+2][lane + 64] + Pw[4*w+3][lane + 64]) * (1.0f/25.0f) + 1e-6f;
        float sm = a0 + a1 + a2;
        #pragma unroll
        for (int o = 16; o; o >>= 1) sm += __shfl_xor_sync(0xffffffffu, sm, o);
        float inv = __fdividef(1.0f, sm);
        logPs[w][lane]      = __logf(a0 * inv);
        logPs[w][lane + 32] = __logf(a1 * inv);
        logPs[w][lane + 64] = __logf(a2 * inv);
    } else if (w < 2*QT) {
        int q = w - QT;
        float v = (lane < NPTS) ? fc[q*NPTS + lane] : 0.f;
        #pragma unroll
        for (int o = 16; o; o >>= 1) v += __shfl_xor_sync(0xffffffffu, v, o);
        if (lane == 0) cls[q] = v * (1.0f / 25.0f);
    }
    __syncthreads();

    // ============ T production (lids 128..159): 16 groups per block =========
    if (isTprod) {
        int bb = (lid - 128) >> 1, half = (lid - 128) & 1;
        if (t == 0) { while (ld_cg(&g_p1) < 128) __nanosleep(32); }
        __syncthreads();
        __threadfence();
        #pragma unroll
        for (int it = 0; it < 3; it++) {
            int item = t + it*512;          // 1536 = 16 groups * 96 vocab
            int gl = item / 96;             // local group 0..15
            int v  = item - gl*96;
            int g  = half*16 + gl;          // group within batch
            const int* ids = &stext[gl*LSEQ];
            float acc = 0.f; int len = 0;
            #pragma unroll
            for (int l = 0; l < LSEQ; l++) {
                int id = ids[l];
                if (id != VOC) {
                    int r = min(max(id, 0), VOC - 1);
                    acc += g_soft[r*VOC + v];
                    len++;
                }
            }
            Ts[g*97 + v] = acc / (float)max(len, 1) + 1e-6f;
            if (v == 0) g_len[bb*NGT + g] = len;
        }
        __syncthreads();
        {   // normalize + sumTlogT: warp w handles group half*16 + w
            int g = half*16 + w;
            float a0 = Ts[g*97 + lane];
            float a1 = Ts[g*97 + 32 + lane];
            float a2 = Ts[g*97 + 64 + lane];
            float s = a0 + a1 + a2;
            #pragma unroll
            for (int o = 16; o; o >>= 1) s += __shfl_xor_sync(0xffffffffu, s, o);
            float inv = 1.0f / s;
            float t0v = a0*inv, t1v = a1*inv, t2v = a2*inv;
            g_T[(size_t)bb*NGT*VOC + g*VOC + lane]      = t0v;
            g_T[(size_t)bb*NGT*VOC + g*VOC + 32 + lane] = t1v;
            g_T[(size_t)bb*NGT*VOC + g*VOC + 64 + lane] = t2v;
            float tl = t0v*__logf(t0v) + t1v*__logf(t1v) + t2v*__logf(t2v);
            #pragma unroll
            for (int o = 16; o; o >>= 1) tl += __shfl_xor_sync(0xffffffffu, tl, o);
            if (lane == 0) g_stt[bb*NGT + g] = tl;
        }
        __threadfence();
        __syncthreads();
        if (t == 0) atomicAdd(&g_pb[bb], 1);
    }

    // ============ p1 gate (instant) then cdist BEFORE the T poll =============
    if (t == 0) { while (ld_cg(&g_p1) < 128) __nanosleep(32); }
    __syncthreads();
    __threadfence();

    u64 acc2[2];
    #pragma unroll
    for (int p = 0; p < 2; p++) acc2[p] = pack2(cls[2*p], cls[2*p+1]);

    #pragma unroll
    for (int db = 0; db < 13; db++) {
        float4 tv = g_tgtT4[db*NCOLS + t];   // already negated
        u64 n0 = pack2(tv.x, tv.x);
        u64 n1 = pack2(tv.y, tv.y);
        u64 n2 = pack2(tv.z, tv.z);
        u64 n3 = pack2(tv.w, tv.w);
        #pragma unroll
        for (int p = 0; p < 2; p++) {
            const ulonglong2* row = (const ulonglong2*)&pp2[p*52 + db*4];
            ulonglong2 ra = row[0];
            ulonglong2 rb = row[1];
            u64 d0 = add2(ra.x, n0) & ABSM;
            u64 d1 = add2(ra.y, n1) & ABSM;
            u64 d2 = add2(rb.x, n2) & ABSM;
            u64 d3 = add2(rb.y, n3) & ABSM;
            acc2[p] = add2(acc2[p], add2(add2(d0, d1), add2(d2, d3)));
        }
    }

    // ============ consume T: per-batch poll, then load own batch's rows =====
    if (t == 0) { while (ld_cg(&g_pb[b]) < 2) __nanosleep(64); }
    __syncthreads();
    __threadfence();
    for (int k = t; k < NGT*VOC; k += 512) {
        int g = k / VOC, v = k - g*VOC;
        Ts[g*97 + v] = g_T[(size_t)b*NGT*VOC + k];
    }
    if (t < NGT) { stt[t] = g_stt[b*NGT + t]; sl[t] = g_len[b*NGT + t]; }
    __syncthreads();

    // ============ phase 3: KL, 4 threads per (q,g) ===========================
    {
        int pid = t >> 2, h = t & 3;        // 128 pairs
        int q = pid >> 5, g = pid & 31;
        float d0 = 0.f;
        const float* tr = &Ts[g*97 + h*24];
        const float* lr = &logPs[q][h*24];
        #pragma unroll 8
        for (int v = 0; v < 24; v++)
            d0 = fmaf(tr[v], lr[v], d0);
        d0 += __shfl_xor_sync(0xffffffffu, d0, 1);
        d0 += __shfl_xor_sync(0xffffffffu, d0, 2);
        if (h == 0) kls[pid] = (sl[g] == 0) ? 100.0f : (stt[g] - d0);
    }
    __syncthreads();

    // ============ final: add kl on diagonal + store ==========================
    bool diag = ((t >> 5) == b);
    int  g    = t & 31;
    #pragma unroll
    for (int p = 0; p < 2; p++) {
        float lo, hi;
        unpack2(lo, hi, acc2[p]);
        int q = 2*p;
        out[(size_t)(b*NQ + q0 + q)*NCOLS + t]     = lo + (diag ? kls[q*NGT + g]     : 0.0f);
        out[(size_t)(b*NQ + q0 + q + 1)*NCOLS + t] = hi + (diag ? kls[(q+1)*NGT + g] : 0.0f);
    }
}

// -----------------------------------------------------------------------------
extern "C" void kernel_launch(void* const* d_in, const int* in_sizes, int n_in,
                              void* d_out, int out_size) {
    const float* pred_logits      = (const float*)d_in[0];
    const float* pred_ctrl_points = (const float*)d_in[1];
    const float* pred_text_logits = (const float*)d_in[2];
    const float* tgt_ctrl_points  = (const float*)d_in[3];
    const int*   tgt_texts        = (const int*)d_in[4];
    const float* pred_centroids   = (const float*)d_in[5];
    float* out = (float*)d_out;

    k_init<<<1, 32>>>();
    k_all<<<dim3(NQ/QT, BS), 512>>>(pred_text_logits, pred_logits,
                                    pred_ctrl_points, tgt_ctrl_points,
                                    tgt_texts, pred_centroids, out);
}

// round 16
// speedup vs baseline: 1.1870x; 1.1870x over previous
#include <cuda_runtime.h>

#define VOC   96
#define BS    16
#define NQ    200
#define NPTS  25
#define NGT   32
#define LSEQ  25
#define NCOLS (BS*NGT)      /* 512 */
#define CDIM  256
#define QT    8
#define NBLK  400

typedef unsigned long long u64;
#define ABSM 0x7FFFFFFF7FFFFFFFULL

// ---------------- scratch (static device globals; no allocation) ------------
__device__ float  g_soft[VOC*VOC];
__device__ float2 g_tgtP2[13*2*NCOLS*2];  // duplicated negated tgt pairs
__device__ float  g_T[BS*NGT*VOC];        // normalized T rows
__device__ float  g_stt[NCOLS];
__device__ int    g_len[NCOLS];
__device__ int    g_p1;                   // stage-1 counter (target 128)
__device__ int    g_pb[BS];               // per-batch T counters (target 2)
__device__ int    g_done;                 // completion counter (self-reset)

// ---------------- helpers ----------------------------------------------------
__device__ __forceinline__ u64 pack2(float lo, float hi) {
    u64 r; asm("mov.b64 %0, {%1, %2};" : "=l"(r) : "f"(lo), "f"(hi)); return r;
}
__device__ __forceinline__ u64 add2(u64 a, u64 b) {
    u64 r; asm("add.rn.f32x2 %0, %1, %2;" : "=l"(r) : "l"(a), "l"(b)); return r;
}
__device__ __forceinline__ void unpack2(float& lo, float& hi, u64 a) {
    asm("mov.b64 {%0, %1}, %2;" : "=f"(lo), "=f"(hi) : "l"(a));
}
__device__ __forceinline__ int ld_cg(const int* p) {
    int v; asm volatile("ld.global.cg.s32 %0, [%1];" : "=r"(v) : "l"(p)); return v;
}

// ---------------- kernel: everything -----------------------------------------
__global__ void __launch_bounds__(512, 3) k_all(
    const float* __restrict__ txt,      // pred_text_logits [16,200,25,97]
    const float* __restrict__ logits,   // pred_logits      [16,200,25]
    const float* __restrict__ predpts,  // pred_ctrl_points [16,200,50]
    const float* __restrict__ tgtpts,   // tgt_ctrl_points  [512,50]
    const int*   __restrict__ texts,    // tgt_texts        [512,25]
    const float* __restrict__ centroids,// [96,256]
    float* __restrict__ out)            // [16,200,512]
{
    __shared__ float  Pw[16][100];
    __shared__ float  logPs[QT][VOC];
    __shared__ float2 pp2[4*52];
    __shared__ float  Ts[NGT*97];
    __shared__ int    stext[16*LSEQ];
    __shared__ float  stt[NGT];
    __shared__ int    sl[NGT];
    __shared__ float  cls[QT];
    __shared__ float  kls[QT*NGT];
    __shared__ float  fc[QT*NPTS];
    __shared__ float  ci[CDIM];
    __shared__ float  srow[VOC], nrow[VOC], stage[VOC];
    __shared__ float  bc1;

    int b   = blockIdx.y;
    int qb  = blockIdx.x;
    int lid = b*25 + qb;            // linear bid, 0..399
    int q0  = qb*QT;
    int t   = threadIdx.x, w = t >> 5, lane = t & 31;
    bool isTprod = (lid >= 128 && lid < 160);

    // ============ producer stage 1 (lids 0..127): soft rows + tgt table =====
    if (lid < 128) {
        if (t < 4*52) {
            int gg = t / 52, d = t - gg*52;
            int grp = lid*4 + gg;
            float v = (d < 50) ? -tgtpts[grp*50 + d] : 0.0f;   // NEGATED
            int db = d >> 2, j = d & 3;
            g_tgtP2[(size_t)((db*2 + (j >> 1))*NCOLS + grp)*2 + (j & 1)]
                = make_float2(v, v);
        }
        if (lid < 96) {
            int i = lid;            // soft_all row i
            if (t < CDIM) ci[t] = centroids[i*CDIM + t];
            __syncthreads();
            float dot[6], nrm[6];
            #pragma unroll
            for (int jj = 0; jj < 6; jj++) { dot[jj] = 0.f; nrm[jj] = 0.f; }
            #pragma unroll
            for (int u = 0; u < 8; u++) {
                float a = ci[lane + u*32];
                #pragma unroll
                for (int jj = 0; jj < 6; jj++) {
                    float bv = centroids[(w + 16*jj)*CDIM + lane + u*32];
                    dot[jj] = fmaf(a,  bv, dot[jj]);
                    nrm[jj] = fmaf(bv, bv, nrm[jj]);
                }
            }
            #pragma unroll
            for (int o = 16; o; o >>= 1) {
                #pragma unroll
                for (int jj = 0; jj < 6; jj++) {
                    dot[jj] += __shfl_xor_sync(0xffffffffu, dot[jj], o);
                    nrm[jj] += __shfl_xor_sync(0xffffffffu, nrm[jj], o);
                }
            }
            if (lane == 0) {
                #pragma unroll
                for (int jj = 0; jj < 6; jj++) {
                    srow[w + 16*jj] = dot[jj];
                    nrow[w + 16*jj] = nrm[jj];
                }
            }
            __syncthreads();
            float e = 0.f;
            if (t < VOC) {
                float sv = srow[t] * rsqrtf(nrow[t] * nrow[i]); // cos in [-1,1]
                e = __expf(sv);                                 // no max needed
                stage[t] = e;
            }
            __syncthreads();
            if (w == 0) {
                float s = stage[lane] + stage[lane+32] + stage[lane+64];
                #pragma unroll
                for (int o = 16; o; o >>= 1) s += __shfl_xor_sync(0xffffffffu, s, o);
                if (lane == 0) bc1 = s;
            }
            __syncthreads();
            if (t < VOC)
                g_soft[i*VOC + t] = (t == i ? 0.85f : 0.0f) + 0.15f * (e / bc1);
        }
        __threadfence();
        __syncthreads();
        if (t == 0) atomicAdd(&g_p1, 1);
    }

    // ============ phase 0: side-data preload =================================
    for (int k = t; k < 4*52; k += 512) {
        int pair = k / 52, d = k - pair*52;
        float v0 = 0.f, v1 = 0.f;
        if (d < 50) {
            v0 = predpts[(size_t)(b*NQ + q0 + 2*pair)*50 + d];
            v1 = predpts[(size_t)(b*NQ + q0 + 2*pair + 1)*50 + d];
        }
        pp2[k] = make_float2(v0, v1);
    }
    if (t < QT*NPTS) {
        float x  = logits[(size_t)(b*NQ + q0)*NPTS + t];
        float pr = __fdividef(1.0f, 1.0f + __expf(-x));
        float pos = 0.25f * (1.f - pr) * (1.f - pr) * (-__logf(pr + 1e-8f));
        float neg = 0.75f * pr * pr * (-__logf(1.f - pr + 1e-8f));
        fc[t] = pos - neg;
    }
    if (isTprod) {
        int bb = (lid - 128) >> 1, half = (lid - 128) & 1;
        for (int k = t; k < 16*LSEQ; k += 512)
            stext[k] = texts[((size_t)bb*NGT + half*16)*LSEQ + k];
    }

    // ============ phase 1: register softmax, 4 rows in flight ================
    {
        int q = w >> 1;
        const float* base = txt + (size_t)(b*NQ + q0 + q) * NPTS * (VOC + 1);
        float pv0 = 0.f, pv1 = 0.f, pv2 = 0.f;
        int p = (w & 1);
        for (; p + 6 < NPTS; p += 8) {
            const float* r0 = base + p*97;
            const float* r1 = base + (p + 2)*97;
            const float* r2 = base + (p + 4)*97;
            const float* r3 = base + (p + 6)*97;
            float e00 = __expf(r0[lane]), e01 = __expf(r0[lane+32]), e02 = __expf(r0[lane+64]);
            float e10 = __expf(r1[lane]), e11 = __expf(r1[lane+32]), e12 = __expf(r1[lane+64]);
            float e20 = __expf(r2[lane]), e21 = __expf(r2[lane+32]), e22 = __expf(r2[lane+64]);
            float e30 = __expf(r3[lane]), e31 = __expf(r3[lane+32]), e32 = __expf(r3[lane+64]);
            float s0 = e00 + e01 + e02;
            float s1 = e10 + e11 + e12;
            float s2 = e20 + e21 + e22;
            float s3 = e30 + e31 + e32;
            if (lane == 0) {
                s0 += __expf(r0[96]);
                s1 += __expf(r1[96]);
                s2 += __expf(r2[96]);
                s3 += __expf(r3[96]);
            }
            #pragma unroll
            for (int o = 16; o; o >>= 1) {
                s0 += __shfl_xor_sync(0xffffffffu, s0, o);
                s1 += __shfl_xor_sync(0xffffffffu, s1, o);
                s2 += __shfl_xor_sync(0xffffffffu, s2, o);
                s3 += __shfl_xor_sync(0xffffffffu, s3, o);
            }
            float i0 = __fdividef(1.0f, s0);
            float i1 = __fdividef(1.0f, s1);
            float i2 = __fdividef(1.0f, s2);
            float i3 = __fdividef(1.0f, s3);
            pv0 = fmaf(e00, i0, pv0); pv0 = fmaf(e10, i1, pv0);
            pv0 = fmaf(e20, i2, pv0); pv0 = fmaf(e30, i3, pv0);
            pv1 = fmaf(e01, i0, pv1); pv1 = fmaf(e11, i1, pv1);
            pv1 = fmaf(e21, i2, pv1); pv1 = fmaf(e31, i3, pv1);
            pv2 = fmaf(e02, i0, pv2); pv2 = fmaf(e12, i1, pv2);
            pv2 = fmaf(e22, i2, pv2); pv2 = fmaf(e32, i3, pv2);
        }
        for (; p < NPTS; p += 2) {
            const float* rA = base + p*97;
            float a0 = __expf(rA[lane]);
            float a1 = __expf(rA[lane + 32]);
            float a2 = __expf(rA[lane + 64]);
            float sa = a0 + a1 + a2;
            if (lane == 0) sa += __expf(rA[96]);
            #pragma unroll
            for (int o = 16; o; o >>= 1) sa += __shfl_xor_sync(0xffffffffu, sa, o);
            float ia = __fdividef(1.0f, sa);
            pv0 = fmaf(a0, ia, pv0);
            pv1 = fmaf(a1, ia, pv1);
            pv2 = fmaf(a2, ia, pv2);
        }
        Pw[w][lane]      = pv0;
        Pw[w][lane + 32] = pv1;
        Pw[w][lane + 64] = pv2;
    }
    __syncthreads();

    // ============ phase 2: logP (warps 0-7), cls (warps 8-15) ================
    if (w < QT) {
        float a0 = (Pw[2*w][lane]    + Pw[2*w+1][lane])    * (1.0f/25.0f) + 1e-6f;
        float a1 = (Pw[2*w][lane+32] + Pw[2*w+1][lane+32]) * (1.0f/25.0f) + 1e-6f;
        float a2 = (Pw[2*w][lane+64] + Pw[2*w+1][lane+64]) * (1.0f/25.0f) + 1e-6f;
        float sm = a0 + a1 + a2;
        #pragma unroll
        for (int o = 16; o; o >>= 1) sm += __shfl_xor_sync(0xffffffffu, sm, o);
        float inv = __fdividef(1.0f, sm);
        logPs[w][lane]      = __logf(a0 * inv);
        logPs[w][lane + 32] = __logf(a1 * inv);
        logPs[w][lane + 64] = __logf(a2 * inv);
    } else {
        int q = w - 8;
        float v = (lane < NPTS) ? fc[q*NPTS + lane] : 0.f;
        #pragma unroll
        for (int o = 16; o; o >>= 1) v += __shfl_xor_sync(0xffffffffu, v, o);
        if (lane == 0) cls[q] = v * (1.0f / 25.0f);
    }
    __syncthreads();

    // ============ T production (lids 128..159): 16 groups per block =========
    if (isTprod) {
        int bb = (lid - 128) >> 1, half = (lid - 128) & 1;
        if (t == 0) { while (ld_cg(&g_p1) < 128) __nanosleep(32); }
        __syncthreads();
        __threadfence();
        #pragma unroll
        for (int it = 0; it < 3; it++) {
            int item = t + it*512;          // 1536 = 16 groups * 96 vocab
            int gl = item / 96;             // local group 0..15
            int v  = item - gl*96;
            int g  = half*16 + gl;          // group within batch
            const int* ids = &stext[gl*LSEQ];
            float acc = 0.f; int len = 0;
            #pragma unroll
            for (int l = 0; l < LSEQ; l++) {
                int id = ids[l];
                if (id != VOC) {
                    int r = min(max(id, 0), VOC - 1);
                    acc += g_soft[r*VOC + v];
                    len++;
                }
            }
            Ts[g*97 + v] = acc / (float)max(len, 1) + 1e-6f;
            if (v == 0) g_len[bb*NGT + g] = len;
        }
        __syncthreads();
        {   // normalize + sumTlogT: warp w handles group half*16 + w
            int g = half*16 + w;
            float a0 = Ts[g*97 + lane];
            float a1 = Ts[g*97 + 32 + lane];
            float a2 = Ts[g*97 + 64 + lane];
            float s = a0 + a1 + a2;
            #pragma unroll
            for (int o = 16; o; o >>= 1) s += __shfl_xor_sync(0xffffffffu, s, o);
            float inv = 1.0f / s;
            float t0v = a0*inv, t1v = a1*inv, t2v = a2*inv;
            g_T[(size_t)bb*NGT*VOC + g*VOC + lane]      = t0v;
            g_T[(size_t)bb*NGT*VOC + g*VOC + 32 + lane] = t1v;
            g_T[(size_t)bb*NGT*VOC + g*VOC + 64 + lane] = t2v;
            float tl = t0v*__logf(t0v) + t1v*__logf(t1v) + t2v*__logf(t2v);
            #pragma unroll
            for (int o = 16; o; o >>= 1) tl += __shfl_xor_sync(0xffffffffu, tl, o);
            if (lane == 0) g_stt[bb*NGT + g] = tl;
        }
        __threadfence();
        __syncthreads();
        if (t == 0) atomicAdd(&g_pb[bb], 1);
    }

    // ============ p1 gate (instant) then cdist BEFORE the T poll =============
    if (t == 0) { while (ld_cg(&g_p1) < 128) __nanosleep(32); }
    __syncthreads();
    __threadfence();

    u64 acc2[4];
    #pragma unroll
    for (int p = 0; p < 4; p++) acc2[p] = pack2(cls[2*p], cls[2*p+1]);

    const ulonglong2* TT = (const ulonglong2*)g_tgtP2;
    #pragma unroll
    for (int db = 0; db < 13; db++) {
        ulonglong2 ta = TT[(db*2 + 0)*NCOLS + t];   // {(x,x),(y,y)} negated
        ulonglong2 tb = TT[(db*2 + 1)*NCOLS + t];   // {(z,z),(w,w)} negated
        #pragma unroll
        for (int p = 0; p < 4; p++) {
            const ulonglong2* row = (const ulonglong2*)&pp2[p*52 + db*4];
            ulonglong2 ra = row[0];
            ulonglong2 rb = row[1];
            u64 d0 = add2(ra.x, ta.x) & ABSM;
            u64 d1 = add2(ra.y, ta.y) & ABSM;
            u64 d2 = add2(rb.x, tb.x) & ABSM;
            u64 d3 = add2(rb.y, tb.y) & ABSM;
            acc2[p] = add2(acc2[p], add2(add2(d0, d1), add2(d2, d3)));
        }
    }

    // ============ consume T: per-batch poll, then load own batch's rows =====
    if (t == 0) { while (ld_cg(&g_pb[b]) < 2) __nanosleep(64); }
    __syncthreads();
    __threadfence();
    for (int k = t; k < NGT*VOC; k += 512) {
        int g = k / VOC, v = k - g*VOC;
        Ts[g*97 + v] = g_T[(size_t)b*NGT*VOC + k];
    }
    if (t < NGT) { stt[t] = g_stt[b*NGT + t]; sl[t] = g_len[b*NGT + t]; }
    __syncthreads();

    // ============ phase 3: KL, 2 threads per (q,g) ===========================
    {
        int pid = t >> 1, h = t & 1;
        int q = pid >> 5, g = pid & 31;
        float d0 = 0.f;
        const float* tr = &Ts[g*97 + h*48];
        const float* lr = &logPs[q][h*48];
        #pragma unroll 8
        for (int v = 0; v < 48; v++)
            d0 = fmaf(tr[v], lr[v], d0);
        d0 += __shfl_xor_sync(0xffffffffu, d0, 1);
        if (h == 0) kls[pid] = (sl[g] == 0) ? 100.0f : (stt[g] - d0);
    }
    __syncthreads();

    // ============ final: add kl on diagonal + store ==========================
    bool diag = ((t >> 5) == b);
    int  g    = t & 31;
    #pragma unroll
    for (int p = 0; p < 4; p++) {
        float lo, hi;
        unpack2(lo, hi, acc2[p]);
        int q = 2*p;
        out[(size_t)(b*NQ + q0 + q)*NCOLS + t]     = lo + (diag ? kls[q*NGT + g]     : 0.0f);
        out[(size_t)(b*NQ + q0 + q + 1)*NCOLS + t] = hi + (diag ? kls[(q+1)*NGT + g] : 0.0f);
    }

    // ============ self-reset for next graph replay ===========================
    // Every block increments g_done only after passing BOTH polls above; the
    // 400th block therefore knows no one still reads the counters and resets.
    __syncthreads();
    if (t == 0) {
        int old = atomicAdd(&g_done, 1);
        if (old == NBLK - 1) {
            g_p1 = 0;
            #pragma unroll
            for (int i = 0; i < BS; i++) g_pb[i] = 0;
            g_done = 0;
            __threadfence();
        }
    }
}

// -----------------------------------------------------------------------------
extern "C" void kernel_launch(void* const* d_in, const int* in_sizes, int n_in,
                              void* d_out, int out_size) {
    const float* pred_logits      = (const float*)d_in[0];
    const float* pred_ctrl_points = (const float*)d_in[1];
    const float* pred_text_logits = (const float*)d_in[2];
    const float* tgt_ctrl_points  = (const float*)d_in[3];
    const int*   tgt_texts        = (const int*)d_in[4];
    const float* pred_centroids   = (const float*)d_in[5];
    float* out = (float*)d_out;

    k_all<<<dim3(NQ/QT, BS), 512>>>(pred_text_logits, pred_logits,
                                    pred_ctrl_points, tgt_ctrl_points,
                                    tgt_texts, pred_centroids, out);
}

// round 17
// speedup vs baseline: 1.1979x; 1.0092x over previous
#include <cuda_runtime.h>

#define VOC   96
#define BS    16
#define NQ    200
#define NPTS  25
#define NGT   32
#define LSEQ  25
#define NCOLS (BS*NGT)      /* 512 */
#define CDIM  256
#define QT    8
#define NBLK  400

typedef unsigned long long u64;
#define ABSM 0x7FFFFFFF7FFFFFFFULL

// ---------------- scratch (static device globals; no allocation) ------------
__device__ float  g_soft[VOC*VOC];
__device__ float2 g_tgtP2[13*2*NCOLS*2];  // duplicated negated tgt pairs
__device__ float  g_T[BS*NGT*VOC];        // normalized T rows
__device__ float  g_stt[NCOLS];
__device__ int    g_len[NCOLS];
__device__ int    g_p1;                   // stage-1 counter (target 128)
__device__ int    g_pb[BS];               // per-batch T counters (target 2)
__device__ int    g_done;                 // completion counter (self-reset)

// ---------------- helpers ----------------------------------------------------
__device__ __forceinline__ u64 pack2(float lo, float hi) {
    u64 r; asm("mov.b64 %0, {%1, %2};" : "=l"(r) : "f"(lo), "f"(hi)); return r;
}
__device__ __forceinline__ u64 add2(u64 a, u64 b) {
    u64 r; asm("add.rn.f32x2 %0, %1, %2;" : "=l"(r) : "l"(a), "l"(b)); return r;
}
__device__ __forceinline__ void unpack2(float& lo, float& hi, u64 a) {
    asm("mov.b64 {%0, %1}, %2;" : "=f"(lo), "=f"(hi) : "l"(a));
}
__device__ __forceinline__ int ld_cg(const int* p) {
    int v; asm volatile("ld.global.cg.s32 %0, [%1];" : "=r"(v) : "l"(p)); return v;
}

// ---------------- kernel: everything -----------------------------------------
__global__ void __launch_bounds__(512, 3) k_all(
    const float* __restrict__ txt,      // pred_text_logits [16,200,25,97]
    const float* __restrict__ logits,   // pred_logits      [16,200,25]
    const float* __restrict__ predpts,  // pred_ctrl_points [16,200,50]
    const float* __restrict__ tgtpts,   // tgt_ctrl_points  [512,50]
    const int*   __restrict__ texts,    // tgt_texts        [512,25]
    const float* __restrict__ centroids,// [96,256]
    float* __restrict__ out)            // [16,200,512]
{
    __shared__ float  Pw[16][100];
    __shared__ float  logPs[QT][VOC];
    __shared__ float2 pp2[4*52];
    __shared__ float  Ts[NGT*97];
    __shared__ int    stext[16*LSEQ];
    __shared__ float  stt[NGT];
    __shared__ int    sl[NGT];
    __shared__ float  cls[QT];
    __shared__ float  kls[QT*NGT];
    __shared__ float  fc[QT*NPTS];
    __shared__ float  ci[CDIM];
    __shared__ float  srow[VOC], nrow[VOC], stage[VOC];
    __shared__ float  bc1;

    int b   = blockIdx.y;
    int qb  = blockIdx.x;
    int lid = b*25 + qb;            // linear bid, 0..399
    int q0  = qb*QT;
    int t   = threadIdx.x, w = t >> 5, lane = t & 31;
    bool isTprod = (lid >= 128 && lid < 160);

    // ============ producer stage 1 (lids 0..127): soft rows + tgt table =====
    if (lid < 128) {
        if (t < 4*52) {
            int gg = t / 52, d = t - gg*52;
            int grp = lid*4 + gg;
            float v = (d < 50) ? -tgtpts[grp*50 + d] : 0.0f;   // NEGATED
            int db = d >> 2, j = d & 3;
            g_tgtP2[(size_t)((db*2 + (j >> 1))*NCOLS + grp)*2 + (j & 1)]
                = make_float2(v, v);
        }
        if (lid < 96) {
            int i = lid;            // soft_all row i
            if (t < CDIM) ci[t] = centroids[i*CDIM + t];
            __syncthreads();
            float dot[6], nrm[6];
            #pragma unroll
            for (int jj = 0; jj < 6; jj++) { dot[jj] = 0.f; nrm[jj] = 0.f; }
            #pragma unroll
            for (int u = 0; u < 8; u++) {
                float a = ci[lane + u*32];
                #pragma unroll
                for (int jj = 0; jj < 6; jj++) {
                    float bv = centroids[(w + 16*jj)*CDIM + lane + u*32];
                    dot[jj] = fmaf(a,  bv, dot[jj]);
                    nrm[jj] = fmaf(bv, bv, nrm[jj]);
                }
            }
            #pragma unroll
            for (int o = 16; o; o >>= 1) {
                #pragma unroll
                for (int jj = 0; jj < 6; jj++) {
                    dot[jj] += __shfl_xor_sync(0xffffffffu, dot[jj], o);
                    nrm[jj] += __shfl_xor_sync(0xffffffffu, nrm[jj], o);
                }
            }
            if (lane == 0) {
                #pragma unroll
                for (int jj = 0; jj < 6; jj++) {
                    srow[w + 16*jj] = dot[jj];
                    nrow[w + 16*jj] = nrm[jj];
                }
            }
            __syncthreads();
            float e = 0.f;
            if (t < VOC) {
                float sv = srow[t] * rsqrtf(nrow[t] * nrow[i]); // cos in [-1,1]
                e = __expf(sv);                                 // no max needed
                stage[t] = e;
            }
            __syncthreads();
            if (w == 0) {
                float s = stage[lane] + stage[lane+32] + stage[lane+64];
                #pragma unroll
                for (int o = 16; o; o >>= 1) s += __shfl_xor_sync(0xffffffffu, s, o);
                if (lane == 0) bc1 = s;
            }
            __syncthreads();
            if (t < VOC)
                g_soft[i*VOC + t] = (t == i ? 0.85f : 0.0f) + 0.15f * (e / bc1);
        }
        __threadfence();
        __syncthreads();
        if (t == 0) atomicAdd(&g_p1, 1);
    }

    // ============ phase 0: side-data preload =================================
    for (int k = t; k < 4*52; k += 512) {
        int pair = k / 52, d = k - pair*52;
        float v0 = 0.f, v1 = 0.f;
        if (d < 50) {
            v0 = predpts[(size_t)(b*NQ + q0 + 2*pair)*50 + d];
            v1 = predpts[(size_t)(b*NQ + q0 + 2*pair + 1)*50 + d];
        }
        pp2[k] = make_float2(v0, v1);
    }
    if (t < QT*NPTS) {
        float x  = logits[(size_t)(b*NQ + q0)*NPTS + t];
        float pr = __fdividef(1.0f, 1.0f + __expf(-x));
        float pos = 0.25f * (1.f - pr) * (1.f - pr) * (-__logf(pr + 1e-8f));
        float neg = 0.75f * pr * pr * (-__logf(1.f - pr + 1e-8f));
        fc[t] = pos - neg;
    }
    if (isTprod) {
        int bb = (lid - 128) >> 1, half = (lid - 128) & 1;
        for (int k = t; k < 16*LSEQ; k += 512)
            stext[k] = texts[((size_t)bb*NGT + half*16)*LSEQ + k];
    }

    // ============ phase 1: register softmax (MUFU exp), 2 rows in flight ====
    {
        int q = w >> 1;
        const float* base = txt + (size_t)(b*NQ + q0 + q) * NPTS * (VOC + 1);
        float pv0 = 0.f, pv1 = 0.f, pv2 = 0.f;
        int p = (w & 1);
        for (; p + 2 < NPTS; p += 4) {
            const float* rA = base + p*(VOC + 1);
            const float* rB = base + (p + 2)*(VOC + 1);
            float a0 = __expf(rA[lane]);
            float a1 = __expf(rA[lane + 32]);
            float a2 = __expf(rA[lane + 64]);
            float a3 = (lane == 0) ? __expf(rA[96]) : 0.f;
            float b0 = __expf(rB[lane]);
            float b1 = __expf(rB[lane + 32]);
            float b2 = __expf(rB[lane + 64]);
            float b3 = (lane == 0) ? __expf(rB[96]) : 0.f;
            float sa = a0 + a1 + a2 + a3;
            float sb = b0 + b1 + b2 + b3;
            #pragma unroll
            for (int o = 16; o; o >>= 1) {
                sa += __shfl_xor_sync(0xffffffffu, sa, o);
                sb += __shfl_xor_sync(0xffffffffu, sb, o);
            }
            float ia = __fdividef(1.0f, sa);
            float ib = __fdividef(1.0f, sb);
            pv0 = fmaf(a0, ia, pv0); pv0 = fmaf(b0, ib, pv0);
            pv1 = fmaf(a1, ia, pv1); pv1 = fmaf(b1, ib, pv1);
            pv2 = fmaf(a2, ia, pv2); pv2 = fmaf(b2, ib, pv2);
        }
        if (p < NPTS) {
            const float* rA = base + p*(VOC + 1);
            float a0 = __expf(rA[lane]);
            float a1 = __expf(rA[lane + 32]);
            float a2 = __expf(rA[lane + 64]);
            float a3 = (lane == 0) ? __expf(rA[96]) : 0.f;
            float sa = a0 + a1 + a2 + a3;
            #pragma unroll
            for (int o = 16; o; o >>= 1) sa += __shfl_xor_sync(0xffffffffu, sa, o);
            float ia = __fdividef(1.0f, sa);
            pv0 = fmaf(a0, ia, pv0);
            pv1 = fmaf(a1, ia, pv1);
            pv2 = fmaf(a2, ia, pv2);
        }
        Pw[w][lane]      = pv0;
        Pw[w][lane + 32] = pv1;
        Pw[w][lane + 64] = pv2;
    }
    __syncthreads();

    // ============ phase 2: logP (warps 0-7), cls (warps 8-15) ================
    if (w < QT) {
        float a0 = (Pw[2*w][lane]    + Pw[2*w+1][lane])    * (1.0f/25.0f) + 1e-6f;
        float a1 = (Pw[2*w][lane+32] + Pw[2*w+1][lane+32]) * (1.0f/25.0f) + 1e-6f;
        float a2 = (Pw[2*w][lane+64] + Pw[2*w+1][lane+64]) * (1.0f/25.0f) + 1e-6f;
        float sm = a0 + a1 + a2;
        #pragma unroll
        for (int o = 16; o; o >>= 1) sm += __shfl_xor_sync(0xffffffffu, sm, o);
        float inv = __fdividef(1.0f, sm);
        logPs[w][lane]      = __logf(a0 * inv);
        logPs[w][lane + 32] = __logf(a1 * inv);
        logPs[w][lane + 64] = __logf(a2 * inv);
    } else {
        int q = w - 8;
        float v = (lane < NPTS) ? fc[q*NPTS + lane] : 0.f;
        #pragma unroll
        for (int o = 16; o; o >>= 1) v += __shfl_xor_sync(0xffffffffu, v, o);
        if (lane == 0) cls[q] = v * (1.0f / 25.0f);
    }
    __syncthreads();

    // ============ T production (lids 128..159): 16 groups per block =========
    if (isTprod) {
        int bb = (lid - 128) >> 1, half = (lid - 128) & 1;
        if (t == 0) { while (ld_cg(&g_p1) < 128) __nanosleep(32); }
        __syncthreads();
        __threadfence();
        #pragma unroll
        for (int it = 0; it < 3; it++) {
            int item = t + it*512;          // 1536 = 16 groups * 96 vocab
            int gl = item / 96;             // local group 0..15
            int v  = item - gl*96;
            int g  = half*16 + gl;          // group within batch
            const int* ids = &stext[gl*LSEQ];
            float acc = 0.f; int len = 0;
            #pragma unroll
            for (int l = 0; l < LSEQ; l++) {
                int id = ids[l];
                if (id != VOC) {
                    int r = min(max(id, 0), VOC - 1);
                    acc += g_soft[r*VOC + v];
                    len++;
                }
            }
            Ts[g*97 + v] = acc / (float)max(len, 1) + 1e-6f;
            if (v == 0) g_len[bb*NGT + g] = len;
        }
        __syncthreads();
        {   // normalize + sumTlogT: warp w handles group half*16 + w
            int g = half*16 + w;
            float a0 = Ts[g*97 + lane];
            float a1 = Ts[g*97 + 32 + lane];
            float a2 = Ts[g*97 + 64 + lane];
            float s = a0 + a1 + a2;
            #pragma unroll
            for (int o = 16; o; o >>= 1) s += __shfl_xor_sync(0xffffffffu, s, o);
            float inv = 1.0f / s;
            float t0v = a0*inv, t1v = a1*inv, t2v = a2*inv;
            g_T[(size_t)bb*NGT*VOC + g*VOC + lane]      = t0v;
            g_T[(size_t)bb*NGT*VOC + g*VOC + 32 + lane] = t1v;
            g_T[(size_t)bb*NGT*VOC + g*VOC + 64 + lane] = t2v;
            float tl = t0v*__logf(t0v) + t1v*__logf(t1v) + t2v*__logf(t2v);
            #pragma unroll
            for (int o = 16; o; o >>= 1) tl += __shfl_xor_sync(0xffffffffu, tl, o);
            if (lane == 0) g_stt[bb*NGT + g] = tl;
        }
        __threadfence();
        __syncthreads();
        if (t == 0) atomicAdd(&g_pb[bb], 1);
    }

    // ============ p1 gate (instant) then cdist BEFORE the T poll =============
    if (t == 0) { while (ld_cg(&g_p1) < 128) __nanosleep(32); }
    __syncthreads();
    __threadfence();

    u64 acc2[4];
    #pragma unroll
    for (int p = 0; p < 4; p++) acc2[p] = pack2(cls[2*p], cls[2*p+1]);

    const ulonglong2* TT = (const ulonglong2*)g_tgtP2;
    #pragma unroll
    for (int db = 0; db < 13; db++) {
        ulonglong2 ta = TT[(db*2 + 0)*NCOLS + t];   // {(x,x),(y,y)} negated
        ulonglong2 tb = TT[(db*2 + 1)*NCOLS + t];   // {(z,z),(w,w)} negated
        #pragma unroll
        for (int p = 0; p < 4; p++) {
            const ulonglong2* row = (const ulonglong2*)&pp2[p*52 + db*4];
            ulonglong2 ra = row[0];
            ulonglong2 rb = row[1];
            u64 d0 = add2(ra.x, ta.x) & ABSM;
            u64 d1 = add2(ra.y, ta.y) & ABSM;
            u64 d2 = add2(rb.x, tb.x) & ABSM;
            u64 d3 = add2(rb.y, tb.y) & ABSM;
            acc2[p] = add2(acc2[p], add2(add2(d0, d1), add2(d2, d3)));
        }
    }

    // ============ early stores: off-diagonal threads need no KL term ========
    float res[8];
    #pragma unroll
    for (int p = 0; p < 4; p++) unpack2(res[2*p], res[2*p + 1], acc2[p]);
    bool diag = ((t >> 5) == b);
    if (!diag) {
        #pragma unroll
        for (int q = 0; q < QT; q++)
            out[(size_t)(b*NQ + q0 + q)*NCOLS + t] = res[q];
    }

    // ============ consume T: per-batch poll, then load own batch's rows =====
    if (t == 0) { while (ld_cg(&g_pb[b]) < 2) __nanosleep(64); }
    __syncthreads();
    __threadfence();
    for (int k = t; k < NGT*VOC; k += 512) {
        int g = k / VOC, v = k - g*VOC;
        Ts[g*97 + v] = g_T[(size_t)b*NGT*VOC + k];
    }
    if (t < NGT) { stt[t] = g_stt[b*NGT + t]; sl[t] = g_len[b*NGT + t]; }
    __syncthreads();

    // ============ phase 3: KL, 2 threads per (q,g), 4 accumulators ==========
    {
        int pid = t >> 1, h = t & 1;
        int q = pid >> 5, g = pid & 31;
        const float* tr = &Ts[g*97 + h*48];
        const float* lr = &logPs[q][h*48];
        float d0 = 0.f, d1 = 0.f, d2 = 0.f, d3 = 0.f;
        #pragma unroll
        for (int v = 0; v < 12; v++) {
            d0 = fmaf(tr[v],      lr[v],      d0);
            d1 = fmaf(tr[v + 12], lr[v + 12], d1);
            d2 = fmaf(tr[v + 24], lr[v + 24], d2);
            d3 = fmaf(tr[v + 36], lr[v + 36], d3);
        }
        float d = (d0 + d1) + (d2 + d3);
        d += __shfl_xor_sync(0xffffffffu, d, 1);
        if (h == 0) kls[pid] = (sl[g] == 0) ? 100.0f : (stt[g] - d);
    }
    __syncthreads();

    // ============ final: diagonal warp adds kl + stores ======================
    if (diag) {
        int g = t & 31;
        #pragma unroll
        for (int q = 0; q < QT; q++)
            out[(size_t)(b*NQ + q0 + q)*NCOLS + t] = res[q] + kls[q*NGT + g];
    }

    // ============ self-reset for next graph replay ===========================
    __syncthreads();
    if (t == 0) {
        int old = atomicAdd(&g_done, 1);
        if (old == NBLK - 1) {
            g_p1 = 0;
            #pragma unroll
            for (int i = 0; i < BS; i++) g_pb[i] = 0;
            g_done = 0;
            __threadfence();
        }
    }
}

// -----------------------------------------------------------------------------
extern "C" void kernel_launch(void* const* d_in, const int* in_sizes, int n_in,
                              void* d_out, int out_size) {
    const float* pred_logits      = (const float*)d_in[0];
    const float* pred_ctrl_points = (const float*)d_in[1];
    const float* pred_text_logits = (const float*)d_in[2];
    const float* tgt_ctrl_points  = (const float*)d_in[3];
    const int*   tgt_texts        = (const int*)d_in[4];
    const float* pred_centroids   = (const float*)d_in[5];
    float* out = (float*)d_out;

    k_all<<<dim3(NQ/QT, BS), 512>>>(pred_text_logits, pred_logits,
                                    pred_ctrl_points, tgt_ctrl_points,
                                    tgt_texts, pred_centroids, out);
}